// round 9
// baseline (speedup 1.0000x reference)
#include <cuda_runtime.h>
#include <cstdint>

#define NN 10000
#define KK 16
#define MT 128              // i rows per i-tile (8 warps x 16 rows)
#define JC 64               // j per stage
#define JSTG 157            // ceil(10000/64)
#define NIT 79
#define TOTAL (NIT * JSTG)  // 12403
#define NCTA 296            // 2 per SM, single wave
#define RBASE 41
#define RREM 267
#define DEPTH 3
#define BT_LD 10048         // == 157*64, padded
#define SLOT_BYTES 32768    // A only: 128 rows x 256B
#define NPREP 40
#define MEAN_NODES 625.0f

__device__ float g_gammaF[KK];
__device__ float g_colsumF[KK];
__device__ float g_result;
__device__ unsigned g_sync;
__device__ unsigned g_done;
__device__ float g_bt[KK * BT_LD];   // (1-Y)^T, k-major, zero padded; L2-resident

// ---------------------------------------------------------------- helpers
__device__ __forceinline__ void cp16(unsigned dst, const void* src) {
    asm volatile("cp.async.cg.shared.global [%0], [%1], 16;" :: "r"(dst), "l"(src) : "memory");
}
__device__ __forceinline__ void zero16(unsigned dst) {
    asm volatile("st.shared.v4.b32 [%0], {%1,%1,%1,%1};" :: "r"(dst), "r"(0) : "memory");
}
__device__ __forceinline__ void ldsm4(uint32_t& r0, uint32_t& r1, uint32_t& r2, uint32_t& r3,
                                      unsigned addr) {
    asm volatile("ldmatrix.sync.aligned.m8n8.x4.shared.b16 {%0,%1,%2,%3}, [%4];"
                 : "=r"(r0), "=r"(r1), "=r"(r2), "=r"(r3) : "r"(addr));
}
__device__ __forceinline__ void mma_tf32(float* d, const uint32_t* a, uint32_t b0, uint32_t b1) {
    asm volatile(
        "mma.sync.aligned.m16n8k8.row.col.f32.tf32.tf32.f32 "
        "{%0,%1,%2,%3}, {%4,%5,%6,%7}, {%8,%9}, {%0,%1,%2,%3};"
        : "+f"(d[0]), "+f"(d[1]), "+f"(d[2]), "+f"(d[3])
        : "r"(a[0]), "r"(a[1]), "r"(a[2]), "r"(a[3]), "r"(b0), "r"(b1));
}

// ---------------------------------------------------------------- main (persistent, fused)
extern __shared__ char dsm[];

__global__ void __launch_bounds__(256, 2) k_main(const float* __restrict__ A,
                                                 const float* __restrict__ Y,
                                                 const float* __restrict__ deg,
                                                 float* __restrict__ out) {
    __shared__ float s_invg[KK];
    __shared__ float sg[KK], sc[KK];

    const int tid  = threadIdx.x;
    const int w    = tid >> 5;
    const int lane = tid & 31;
    const unsigned smBase = (unsigned)__cvta_generic_to_shared(dsm);

    // ================= fused prep (first NPREP CTAs) + device barrier =================
    if (blockIdx.x < NPREP) {
        const int j = blockIdx.x * 256 + tid;
        float y[KK];
        float d = 0.f;
        const bool v = (j < NN);
        if (v) {
            d = deg[j];
            const float4* y4 = (const float4*)(Y + (size_t)j * KK);
#pragma unroll
            for (int q = 0; q < 4; q++) {
                float4 vv = y4[q];
                y[4*q+0] = vv.x; y[4*q+1] = vv.y; y[4*q+2] = vv.z; y[4*q+3] = vv.w;
            }
        } else {
#pragma unroll
            for (int k = 0; k < KK; k++) y[k] = 0.f;
        }
        if (j < BT_LD) {
#pragma unroll
            for (int k = 0; k < KK; k++)
                g_bt[(size_t)k * BT_LD + j] = v ? (1.0f - y[k]) : 0.f;
        }
        if (tid < KK) { sg[tid] = 0.f; sc[tid] = 0.f; }
        __syncthreads();
#pragma unroll
        for (int k = 0; k < KK; k++) {
            float gv = y[k] * d, cv = y[k];
#pragma unroll
            for (int o = 16; o; o >>= 1) {
                gv += __shfl_xor_sync(0xffffffffu, gv, o);
                cv += __shfl_xor_sync(0xffffffffu, cv, o);
            }
            if (lane == 0) { atomicAdd(&sg[k], gv); atomicAdd(&sc[k], cv); }
        }
        __syncthreads();
        if (tid < KK) {
            atomicAdd(&g_gammaF[tid], sg[tid]);
            atomicAdd(&g_colsumF[tid], sc[tid]);
        }
        __syncthreads();
        if (tid == 0) { __threadfence(); atomicAdd(&g_sync, 1u); }
    } else {
        if (tid == 0) atomicAdd(&g_sync, 1u);
    }
    if (tid == 0) {
        while (atomicAdd(&g_sync, 0u) < NCTA) __nanosleep(64);
    }
    __syncthreads();
    __threadfence();

    if (tid < KK) s_invg[tid] = 1.0f / atomicAdd(&g_gammaF[tid], 0.0f);
    __syncthreads();   // s_invg ready; after this the loop is barrier-free

    // ================= warp-private pipelines: ZERO intra-loop barriers ==============
    const int bid  = blockIdx.x;
    const int sid0 = bid * RBASE + (bid < RREM ? bid : RREM);
    const int len  = RBASE + (bid < RREM ? 1 : 0);

    // A fill geometry (warp-private rows w*16 .. w*16+15):
    //   chunk q (0..7): row rr = 2q + (lane>>4), chunk col u = lane&15
    const int hl = lane >> 4;
    const int u  = lane & 15;
    // A ldmatrix geometry (within own 16 rows)
    const int m    = lane >> 3;
    const int rsub = lane & 7;
    const int rA   = w * 16 + ((m & 1) << 3) + rsub;
    const int pA   = m >> 1;
    const unsigned aOffBase = (unsigned)(rA * 256);
    const unsigned aXor     = (unsigned)((rA & 7) * 16);
    // B direct-from-L2 pointers (fragment layout: b0=B[k=lane%4][n=lane/4], b1=+4)
    const float* btp0 = g_bt + (size_t)(lane >> 2) * BT_LD + (lane & 3);
    const float* btp1 = btp0 + (size_t)8 * BT_LD;

    float acc0[4] = {0.f, 0.f, 0.f, 0.f};
    float acc1[4] = {0.f, 0.f, 0.f, 0.f};

    // warp-local cursors
    int it  = sid0 / JSTG;
    int js  = sid0 - it * JSTG;
    int itF = it, jsF = js;

    // per-warp fill of OWN 16 rows of a slot (8 cp.async per lane, 1 commit)
    auto fill = [&](int slot) {
        const int i0 = itF * MT + w * 16;
        const int j0 = jsF * JC;
        const unsigned sm = smBase + (unsigned)(slot * SLOT_BYTES) + (unsigned)(w * 16 * 256);
        const int jc = j0 + u * 4;
        const bool jok = (jc < NN);
        const float* src = A + (size_t)(i0 + hl) * NN + jc;
#pragma unroll
        for (int q = 0; q < 8; q++) {
            const int rr = 2 * q + hl;
            unsigned dst = sm + (unsigned)(rr * 256) + (unsigned)((u ^ (rr & 7)) * 16);
            if (jok && (i0 + rr) < NN)
                cp16(dst, (const char*)(src + (size_t)2 * q * NN));
            else
                zero16(dst);
        }
        asm volatile("cp.async.commit_group;" ::: "memory");
        if (++jsF == JSTG) { jsF = 0; itF++; }
    };

    // prologue: 2 warp-private fills
    if (0 < len) fill(0); else asm volatile("cp.async.commit_group;" ::: "memory");
    if (1 < len) fill(1); else asm volatile("cp.async.commit_group;" ::: "memory");

    int slotF = 2;
    int slotC = 0;

    for (int t = 0; t < len; t++) {
        // B values for stage t: 32 scalar L2-hit loads, issued before the A wait
        const int j0c = js * JC;
        float bb[32];
#pragma unroll
        for (int kk = 0; kk < 8; kk++) {
            const int jb = j0c + 8 * kk;
            bb[4*kk+0] = btp0[jb];
            bb[4*kk+1] = btp0[jb + 4];
            bb[4*kk+2] = btp1[jb];
            bb[4*kk+3] = btp1[jb + 4];
        }

        // prefetch own rows of the slot freed at iter t-1 (warp-local WAR: safe)
        if (t + 2 < len) fill(slotF);
        else asm volatile("cp.async.commit_group;" ::: "memory");
        if (++slotF == DEPTH) slotF = 0;

        // own A copies for stage t complete; syncwarp publishes cross-lane smem writes
        asm volatile("cp.async.wait_group %0;" :: "n"(DEPTH - 1) : "memory");
        __syncwarp();

        const unsigned sm = smBase + (unsigned)(slotC * SLOT_BYTES);
        if (++slotC == DEPTH) slotC = 0;
#pragma unroll
        for (int kk = 0; kk < 8; kk++) {
            uint32_t a[4];
            unsigned aAddr = sm + aOffBase + ((unsigned)((2 * kk + pA) * 16) ^ aXor);
            ldsm4(a[0], a[1], a[2], a[3], aAddr);
            mma_tf32(acc0, a, __float_as_uint(bb[4*kk+0]), __float_as_uint(bb[4*kk+1]));
            mma_tf32(acc1, a, __float_as_uint(bb[4*kk+2]), __float_as_uint(bb[4*kk+3]));
        }

        // flush at i-tile boundary or end of run (warp-local)
        if (js == JSTG - 1 || t == len - 1) {
            const int i0 = it * MT;
            const int q  = lane & 3;
            const int rAi = i0 + w * 16 + (lane >> 2);
            const int rBi = rAi + 8;
            float part = 0.f;
            if (rAi < NN) {
                const float* yr = Y + (size_t)rAi * KK;
                part += acc0[0] * yr[2*q]     * s_invg[2*q];
                part += acc0[1] * yr[2*q + 1] * s_invg[2*q + 1];
                part += acc1[0] * yr[8 + 2*q] * s_invg[8 + 2*q];
                part += acc1[1] * yr[9 + 2*q] * s_invg[9 + 2*q];
            }
            if (rBi < NN) {
                const float* yr = Y + (size_t)rBi * KK;
                part += acc0[2] * yr[2*q]     * s_invg[2*q];
                part += acc0[3] * yr[2*q + 1] * s_invg[2*q + 1];
                part += acc1[2] * yr[8 + 2*q] * s_invg[8 + 2*q];
                part += acc1[3] * yr[9 + 2*q] * s_invg[9 + 2*q];
            }
#pragma unroll
            for (int o = 16; o; o >>= 1) part += __shfl_xor_sync(0xffffffffu, part, o);
            if (lane == 0) atomicAdd(&g_result, part);
#pragma unroll
            for (int z = 0; z < 4; z++) { acc0[z] = 0.f; acc1[z] = 0.f; }
        }
        if (++js == JSTG) { js = 0; it++; }
    }

    __syncthreads();   // all warps' atomics to g_result issued before the ticket

    // ================= finalize: last CTA writes output + resets state =================
    if (w == 0) {
        float ep = 0.f;
        if (lane < KK) {
            float c = atomicAdd(&g_colsumF[lane], 0.0f) - MEAN_NODES;
            ep = c * c;
        }
#pragma unroll
        for (int o = 16; o; o >>= 1) ep += __shfl_xor_sync(0xffffffffu, ep, o);

        if (lane == 0) {
            __threadfence();
            unsigned prev = atomicAdd(&g_done, 1u);
            if (prev == NCTA - 1) {
                float ec = atomicAdd(&g_result, 0.0f);
                out[0] = ec + ep;
                g_result = 0.f;
                g_sync = 0u;
                g_done = 0u;
#pragma unroll
                for (int k = 0; k < KK; k++) { g_gammaF[k] = 0.f; g_colsumF[k] = 0.f; }
                __threadfence();
            }
        }
    }
}

// ---------------------------------------------------------------- launcher
extern "C" void kernel_launch(void* const* d_in, const int* in_sizes, int n_in,
                              void* d_out, int out_size) {
    const float* Y = nullptr;
    const float* A = nullptr;
    const float* deg = nullptr;
    for (int i = 0; i < n_in; i++) {
        if (in_sizes[i] == NN * NN)       A = (const float*)d_in[i];
        else if (in_sizes[i] == NN * KK)  Y = (const float*)d_in[i];
        else if (in_sizes[i] == NN)       deg = (const float*)d_in[i];
    }
    if (!Y)   Y = (const float*)d_in[0];
    if (!A)   A = (const float*)d_in[1];
    if (!deg) deg = (const float*)d_in[2];

    const int SMEM_DYN = DEPTH * SLOT_BYTES;   // 98304
    cudaFuncSetAttribute(k_main, cudaFuncAttributeMaxDynamicSharedMemorySize, SMEM_DYN);

    k_main<<<NCTA, 256, SMEM_DYN>>>(A, Y, deg, (float*)d_out);
}

// round 10
// speedup vs baseline: 1.7550x; 1.7550x over previous
#include <cuda_runtime.h>
#include <cstdint>

#define NN 10000
#define KK 16
#define MT 128              // i rows per i-tile (8 warps x 16)
#define JC 64               // j per stage
#define JSTG 157            // ceil(10000/64)
#define NIT 79
#define TOTAL (NIT * JSTG)  // 12403
#define NCTA 296            // 2 per SM, single wave
#define RBASE 41
#define RREM 267
#define DEPTH 3
#define BT_LD 10048
#define SLOT_BYTES 36864    // 32KB A + 4KB B
#define NPB 40
#define MEAN_NODES 625.0f

__device__ float g_partg[NPB * KK];
__device__ float g_partc[NPB * KK];
__device__ float g_result;
__device__ unsigned g_done;          // zero-initialized; self-resetting ticket
__device__ float g_bt[KK * BT_LD];   // (1-Y)^T, k-major, zero padded beyond j=NN

// ---------------------------------------------------------------- helpers
__device__ __forceinline__ void cp16(unsigned dst, const void* src) {
    asm volatile("cp.async.cg.shared.global [%0], [%1], 16;" :: "r"(dst), "l"(src) : "memory");
}
__device__ __forceinline__ void zero16(unsigned dst) {
    asm volatile("st.shared.v4.b32 [%0], {%1,%1,%1,%1};" :: "r"(dst), "r"(0) : "memory");
}
__device__ __forceinline__ void ldsm4(uint32_t& r0, uint32_t& r1, uint32_t& r2, uint32_t& r3,
                                      unsigned addr) {
    asm volatile("ldmatrix.sync.aligned.m8n8.x4.shared.b16 {%0,%1,%2,%3}, [%4];"
                 : "=r"(r0), "=r"(r1), "=r"(r2), "=r"(r3) : "r"(addr));
}
__device__ __forceinline__ void mma_tf32(float* d, const uint32_t* a, uint32_t b0, uint32_t b1) {
    asm volatile(
        "mma.sync.aligned.m16n8k8.row.col.f32.tf32.tf32.f32 "
        "{%0,%1,%2,%3}, {%4,%5,%6,%7}, {%8,%9}, {%0,%1,%2,%3};"
        : "+f"(d[0]), "+f"(d[1]), "+f"(d[2]), "+f"(d[3])
        : "r"(a[0]), "r"(a[1]), "r"(a[2]), "r"(a[3]), "r"(b0), "r"(b1));
}

// ---------------------------------------------------------------- fused prep
__global__ void k_prep(const float* __restrict__ Y, const float* __restrict__ deg) {
    const int t = threadIdx.x;
    const int j = blockIdx.x * 256 + t;
    if (blockIdx.x == 0 && t == 0) g_result = 0.f;

    float y[KK];
    float d = 0.f;
    const bool v = (j < NN);
    if (v) {
        d = deg[j];
        const float4* y4 = (const float4*)(Y + (size_t)j * KK);
#pragma unroll
        for (int q = 0; q < 4; q++) {
            float4 vv = y4[q];
            y[4*q+0] = vv.x; y[4*q+1] = vv.y; y[4*q+2] = vv.z; y[4*q+3] = vv.w;
        }
    } else {
#pragma unroll
        for (int k = 0; k < KK; k++) y[k] = 0.f;
    }

    if (j < BT_LD) {
#pragma unroll
        for (int k = 0; k < KK; k++)
            g_bt[(size_t)k * BT_LD + j] = v ? (1.0f - y[k]) : 0.f;
    }

    __shared__ float sg[KK], sc[KK];
    if (t < KK) { sg[t] = 0.f; sc[t] = 0.f; }
    __syncthreads();
#pragma unroll
    for (int k = 0; k < KK; k++) {
        float gv = y[k] * d, cv = y[k];
#pragma unroll
        for (int o = 16; o; o >>= 1) {
            gv += __shfl_xor_sync(0xffffffffu, gv, o);
            cv += __shfl_xor_sync(0xffffffffu, cv, o);
        }
        if ((t & 31) == 0) { atomicAdd(&sg[k], gv); atomicAdd(&sc[k], cv); }
    }
    __syncthreads();
    if (t < KK) {
        g_partg[blockIdx.x * KK + t] = sg[t];
        g_partc[blockIdx.x * KK + t] = sc[t];
    }
}

// ---------------------------------------------------------------- main (persistent)
extern __shared__ char dsm[];

__global__ void __launch_bounds__(256, 2) k_main(const float* __restrict__ A,
                                                 const float* __restrict__ Y,
                                                 float* __restrict__ out) {
    __shared__ float s_invg[KK];

    const int tid  = threadIdx.x;
    const int w    = tid >> 5;
    const int lane = tid & 31;
    const unsigned smBase = (unsigned)__cvta_generic_to_shared(dsm);

    if (tid < KK) {
        float g = 0.f;
#pragma unroll 8
        for (int b = 0; b < NPB; b++) g += g_partg[b * KK + tid];
        s_invg[tid] = 1.0f / g;
    }

    const int bid  = blockIdx.x;
    const int sid0 = bid * RBASE + (bid < RREM ? bid : RREM);
    const int len  = RBASE + (bid < RREM ? 1 : 0);

    // ---- per-thread ldmatrix source geometry (validated R3-R6) ----
    const int m    = lane >> 3;
    const int rsub = lane & 7;
    const int rA   = w * 16 + ((m & 1) << 3) + rsub;
    const int pA   = m >> 1;
    const unsigned aOffBase = (unsigned)(rA * 256);
    const unsigned aXor     = (unsigned)((rA & 7) * 16);
    const int rB   = ((m >> 1) << 3) + rsub;
    const int pB   = m & 1;
    const unsigned bOffBase = 32768u + (unsigned)(rB * 256);
    const unsigned bXor     = (unsigned)((rB & 7) * 16);

    // ---- fill geometry (fast path precompute) ----
    const int fr0 = tid >> 4;          // base row for this thread's chunks
    const int fu  = tid & 15;          // chunk column
    const unsigned fDst0 = (unsigned)(fr0 * 256) + (unsigned)((fu ^ (fr0 & 7)) * 16);
    // B fill: one chunk per thread
    const int fbr = tid >> 4, fbu = tid & 15;
    const unsigned fbDst = 32768u + (unsigned)(fbr * 256) + (unsigned)((fbu ^ (fbr & 7)) * 16);
    const float* fbSrcBase = g_bt + (size_t)fbr * BT_LD + fbu * 4;

    float acc0[4] = {0.f, 0.f, 0.f, 0.f};
    float acc1[4] = {0.f, 0.f, 0.f, 0.f};

    // incremental cursors: consume (it, js) and fill (itF, jsF)
    int it  = sid0 / JSTG;
    int js  = sid0 - it * JSTG;
    int itF = it, jsF = js;

    auto fill = [&](int slot) {
        const int i0 = itF * MT;
        const int j0 = jsF * JC;
        const unsigned sm = smBase + (unsigned)(slot * SLOT_BYTES);
        if (i0 + MT <= NN && j0 + JC <= NN) {
            // interior fast path: 8 unconditional cp16, constant strides
            const char* src = (const char*)(A + (size_t)(i0 + fr0) * NN + j0 + fu * 4);
            unsigned dst = sm + fDst0;
#pragma unroll
            for (int q = 0; q < 8; q++) {
                cp16(dst, src);
                src += (size_t)16 * NN * 4;
                dst += 4096u;
            }
        } else {
#pragma unroll
            for (int c = tid; c < 2048; c += 256) {
                int r = c >> 4, u = c & 15;
                unsigned dst = sm + (unsigned)(r * 256) + (unsigned)((u ^ (r & 7)) * 16);
                int i = i0 + r;
                int jc = j0 + u * 4;
                if (i < NN && jc < NN)
                    cp16(dst, (const char*)(A + (size_t)i * NN + jc));
                else
                    zero16(dst);
            }
        }
        // B: padded scratch always valid
        cp16(sm + fbDst, (const char*)(fbSrcBase + j0));
        asm volatile("cp.async.commit_group;" ::: "memory");
        if (++jsF == JSTG) { jsF = 0; itF++; }
    };

    // prologue: 2 fills
    if (0 < len) fill(0); else asm volatile("cp.async.commit_group;" ::: "memory");
    if (1 < len) fill(1); else asm volatile("cp.async.commit_group;" ::: "memory");

    int slotF = 2;   // slot for in-loop fill: (t+2) % 3
    int slotC = 0;   // slot for compute: t % 3

    for (int t = 0; t < len; t++) {
        // stage t ready (pending {f_t, f_{t+1}} -> wait leaves 1)
        asm volatile("cp.async.wait_group 1;" ::: "memory");
        // SINGLE barrier: publishes stage-t data to all warps AND proves every
        // warp finished compute(t-1) -> slot (t+2)%3 == (t-1)%3 is WAR-safe.
        __syncthreads();

        // fill before compute: DMA overlaps this stage's math
        if (t + 2 < len) fill(slotF);
        else asm volatile("cp.async.commit_group;" ::: "memory");
        if (++slotF == DEPTH) slotF = 0;

        const unsigned sm = smBase + (unsigned)(slotC * SLOT_BYTES);
        if (++slotC == DEPTH) slotC = 0;
#pragma unroll
        for (int kk = 0; kk < 8; kk++) {
            uint32_t a[4], b[4];
            unsigned aAddr = sm + aOffBase + ((unsigned)((2 * kk + pA) * 16) ^ aXor);
            unsigned bAddr = sm + bOffBase + ((unsigned)((2 * kk + pB) * 16) ^ bXor);
            ldsm4(a[0], a[1], a[2], a[3], aAddr);
            ldsm4(b[0], b[1], b[2], b[3], bAddr);
            mma_tf32(acc0, a, b[0], b[1]);
            mma_tf32(acc1, a, b[2], b[3]);
        }

        // flush at i-tile boundary or end of run
        if (js == JSTG - 1 || t == len - 1) {
            const int i0 = it * MT;
            const int q  = lane & 3;
            const int rAi = i0 + w * 16 + (lane >> 2);
            const int rBi = rAi + 8;
            float part = 0.f;
            if (rAi < NN) {
                const float* yr = Y + (size_t)rAi * KK;
                part += acc0[0] * yr[2*q]     * s_invg[2*q];
                part += acc0[1] * yr[2*q + 1] * s_invg[2*q + 1];
                part += acc1[0] * yr[8 + 2*q] * s_invg[8 + 2*q];
                part += acc1[1] * yr[9 + 2*q] * s_invg[9 + 2*q];
            }
            if (rBi < NN) {
                const float* yr = Y + (size_t)rBi * KK;
                part += acc0[2] * yr[2*q]     * s_invg[2*q];
                part += acc0[3] * yr[2*q + 1] * s_invg[2*q + 1];
                part += acc1[2] * yr[8 + 2*q] * s_invg[8 + 2*q];
                part += acc1[3] * yr[9 + 2*q] * s_invg[9 + 2*q];
            }
#pragma unroll
            for (int o = 16; o; o >>= 1) part += __shfl_xor_sync(0xffffffffu, part, o);
            if (lane == 0) atomicAdd(&g_result, part);
#pragma unroll
            for (int z = 0; z < 4; z++) { acc0[z] = 0.f; acc1[z] = 0.f; }
        }
        if (++js == JSTG) { js = 0; it++; }
    }

    // ---- finalization: last CTA writes out (single resident wave) ----
    if (w == 0) {
        float ep = 0.f;
        if (lane < KK) {
            float c = 0.f;
#pragma unroll 8
            for (int b = 0; b < NPB; b++) c += g_partc[b * KK + lane];
            c -= MEAN_NODES;
            ep = c * c;
        }
#pragma unroll
        for (int o = 16; o; o >>= 1) ep += __shfl_xor_sync(0xffffffffu, ep, o);

        if (lane == 0) {
            __threadfence();
            unsigned prev = atomicAdd(&g_done, 1u);
            if (prev == NCTA - 1) {
                g_done = 0;   // reset for graph replay
                float ec = atomicAdd(&g_result, 0.0f);  // coherent read
                out[0] = ec + ep;
            }
        }
    }
}

// ---------------------------------------------------------------- launcher
extern "C" void kernel_launch(void* const* d_in, const int* in_sizes, int n_in,
                              void* d_out, int out_size) {
    const float* Y = nullptr;
    const float* A = nullptr;
    const float* deg = nullptr;
    for (int i = 0; i < n_in; i++) {
        if (in_sizes[i] == NN * NN)       A = (const float*)d_in[i];
        else if (in_sizes[i] == NN * KK)  Y = (const float*)d_in[i];
        else if (in_sizes[i] == NN)       deg = (const float*)d_in[i];
    }
    if (!Y)   Y = (const float*)d_in[0];
    if (!A)   A = (const float*)d_in[1];
    if (!deg) deg = (const float*)d_in[2];

    const int SMEM_DYN = DEPTH * SLOT_BYTES;   // 110592
    cudaFuncSetAttribute(k_main, cudaFuncAttributeMaxDynamicSharedMemorySize, SMEM_DYN);

    k_prep<<<NPB, 256>>>(Y, deg);
    k_main<<<NCTA, 256, SMEM_DYN>>>(A, Y, (float*)d_out);
}